// round 5
// baseline (speedup 1.0000x reference)
#include <cuda_runtime.h>

#define NQ     12
#define DIM    4096
#define NPAIR  2048
#define TPB    256
#define NPARAM 240          // 12 * 4 * 5
#define NLAYER 4

// Bank-conflict swizzle: XOR bit4 into bits 0-3. For any pair-axis a, the
// 16 half-warp addresses' (%16) become a bijection of lane bits -> LDS.64
// conflict-free for all axes.
#define PHYS(i) ((i) ^ ((((i) >> 4) & 1) * 0xF))

__device__ __forceinline__ void app(float2 &s0, float2 &s1,
        const float2 M00, const float2 M01, const float2 M10, const float2 M11) {
    float n0x = fmaf(M00.x, s0.x, fmaf(-M00.y, s0.y, fmaf(M01.x, s1.x, -M01.y * s1.y)));
    float n0y = fmaf(M00.x, s0.y, fmaf( M00.y, s0.x, fmaf(M01.x, s1.y,  M01.y * s1.x)));
    float n1x = fmaf(M10.x, s0.x, fmaf(-M10.y, s0.y, fmaf(M11.x, s1.x, -M11.y * s1.y)));
    float n1y = fmaf(M10.x, s0.y, fmaf( M10.y, s0.x, fmaf(M11.x, s1.y,  M11.y * s1.x)));
    s0 = make_float2(n0x, n0y);
    s1 = make_float2(n1x, n1y);
}

// RX(theta): [[c, -i s],[-i s, c]]
__device__ __forceinline__ void appRX(float2 &s0, float2 &s1, float c, float s) {
    float2 n0 = make_float2(fmaf(c, s0.x,  s * s1.y), fmaf(c, s0.y, -s * s1.x));
    float2 n1 = make_float2(fmaf(c, s1.x,  s * s0.y), fmaf(c, s1.y, -s * s0.x));
    s0 = n0; s1 = n1;
}

__device__ __forceinline__ float2 cmulf(float2 a, float2 b) {
    return make_float2(fmaf(a.x, b.x, -a.y * b.y), fmaf(a.x, b.y, a.y * b.x));
}

// M = Rz * Ry * Rx (gates applied in order Rx, Ry, Rz)
__device__ __forceinline__ void build_u(float cx, float sx, float cy, float sy,
                                        float cz, float sz,
        float2 &M00, float2 &M01, float2 &M10, float2 &M11) {
    float2 A00 = make_float2( cy * cx,  sy * sx);
    float2 A01 = make_float2(-sy * cx, -cy * sx);
    float2 A10 = make_float2( sy * cx, -cy * sx);
    float2 A11 = make_float2( cy * cx, -sy * sx);
    float2 ez  = make_float2(cz, -sz);
    float2 ezc = make_float2(cz,  sz);
    M00 = cmulf(ez,  A00); M01 = cmulf(ez,  A01);
    M10 = cmulf(ezc, A10); M11 = cmulf(ezc, A11);
}

// CRX-only pass: pairs across `axis`, RX applied where index bit `cond` == 1.
__device__ __forceinline__ void crx_pass(float2 *st, int t, int axis, int cond,
                                         float c, float s) {
    const int bit = 1 << axis, mask = bit - 1;
    #pragma unroll
    for (int r = 0; r < NPAIR / TPB; r++) {
        int j  = t + r * TPB;
        int i0 = ((j & ~mask) << 1) | (j & mask);
        if ((i0 >> cond) & 1) {
            int p0 = PHYS(i0), p1 = PHYS(i0 | bit);
            float2 s0 = st[p0], s1 = st[p1];
            appRX(s0, s1, c, s);
            st[p0] = s0; st[p1] = s1;
        }
    }
    __syncthreads();
}

__device__ __forceinline__ void wred(float *rbuf, int o, int warp, int lane,
                                     float rr, float ri, float rz) {
    #pragma unroll
    for (int off = 16; off; off >>= 1) {
        rr += __shfl_down_sync(0xffffffffu, rr, off);
        ri += __shfl_down_sync(0xffffffffu, ri, off);
        rz += __shfl_down_sync(0xffffffffu, rz, off);
    }
    if (lane == 0) {
        rbuf[o * 8 + warp]       = rr;   // x slot  (out idx o)
        rbuf[96 + o * 8 + warp]  = ri;   // y slot  (out idx 12+o)
        rbuf[192 + o * 8 + warp] = rz;   // z slot  (out idx 24+o)
    }
}

__global__ __launch_bounds__(TPB) void qfe_kernel(
    const float* __restrict__ params,   // (B, 240)
    const float* __restrict__ inputs,   // (B, 12)
    float* __restrict__ out)            // (B, 36)
{
    __shared__ float2 st[DIM];          // 32 KB statevector (swizzled layout)
    __shared__ float  cs[NPARAM], sn[NPARAM];   // cos/sin of half-angles
    __shared__ float  eic[NQ], eis[NQ];         // embedding cos/sin
    __shared__ float  rbuf[288];                // 36 outputs x 8 warps

    const int b = blockIdx.x;
    const int t = threadIdx.x;
    const int lane = t & 31, warp = t >> 5;

    // ---- stage all trig once per block
    if (t < NPARAM) {
        float h = 0.5f * params[b * NPARAM + t];
        sincosf(h, &sn[t], &cs[t]);
    } else if (t < NPARAM + NQ) {
        int i = t - NPARAM;
        float h = 0.5f * inputs[b * NQ + i];
        sincosf(h, &eis[i], &eic[i]);
    }
    __syncthreads();

    float2 v[16];

    #pragma unroll 1
    for (int L = 0; L < NLAYER; L++) {
        const int base = 60 * L;

        // ================= P1: local mega-pass =================
        // init (L==0) or load; U0-U3 (k bits); F0=CRX(0,1), F1=CRX(1,2), F2=CRX(2,3)
        if (L == 0) {
            // product state: RY(input_w) embedding on |0...0>
            float tp = 1.0f;
            #pragma unroll
            for (int w = 4; w < 12; w++)
                tp *= ((t >> (11 - w)) & 1) ? eis[w] : eic[w];
            #pragma unroll
            for (int k = 0; k < 16; k++) {
                float a = tp;
                #pragma unroll
                for (int w = 0; w < 4; w++)
                    a *= ((k >> (3 - w)) & 1) ? eis[w] : eic[w];
                v[k] = make_float2(a, 0.0f);
            }
        } else {
            #pragma unroll
            for (int k = 0; k < 16; k++) v[k] = st[PHYS(t + (k << 8))];
        }
        // U0..U3: wire w <-> k bit (3-w)
        #pragma unroll
        for (int w = 0; w < 4; w++) {
            int pi = base + 3 * w;
            float2 M00, M01, M10, M11;
            build_u(cs[pi], sn[pi], cs[pi + 1], sn[pi + 1], cs[pi + 2], sn[pi + 2],
                    M00, M01, M10, M11);
            int kbit = 1 << (3 - w);
            #pragma unroll
            for (int k = 0; k < 16; k++)
                if (!(k & kbit)) app(v[k], v[k | kbit], M00, M01, M10, M11);
        }
        // F0,F1,F2: ctrl k bit (3-i), tgt k bit (2-i)
        #pragma unroll
        for (int i = 0; i < 3; i++) {
            int pi = base + 36 + i;
            float c = cs[pi], s = sn[pi];
            int cb = 1 << (3 - i), tb = 1 << (2 - i);
            #pragma unroll
            for (int k = 0; k < 16; k++)
                if ((k & cb) && !(k & tb)) appRX(v[k], v[k | tb], c, s);
        }
        #pragma unroll
        for (int k = 0; k < 16; k++) st[PHYS(t + (k << 8))] = v[k];
        __syncthreads();

        // ===== P2..P9: U_w fused with F_{w-1}=CRX(w-1,w), w=4..11 =====
        // pair axis = 11-w (target bit), ctrl bit = axis+1
        #pragma unroll
        for (int w = 4; w < 12; w++) {
            const int axis = 11 - w, cond = axis + 1;
            const int pi = base + 3 * w, fi = base + 36 + (w - 1);
            float2 A00, A01, A10, A11;
            build_u(cs[pi], sn[pi], cs[pi + 1], sn[pi + 1], cs[pi + 2], sn[pi + 2],
                    A00, A01, A10, A11);
            const float fc = cs[fi], fs = sn[fi];
            const int bit = 1 << axis, mask = bit - 1;
            #pragma unroll
            for (int r = 0; r < NPAIR / TPB; r++) {
                int j  = t + r * TPB;
                int i0 = ((j & ~mask) << 1) | (j & mask);
                int p0 = PHYS(i0), p1 = PHYS(i0 | bit);
                float2 s0 = st[p0], s1 = st[p1];
                app(s0, s1, A00, A01, A10, A11);
                if ((i0 >> cond) & 1) appRX(s0, s1, fc, fs);
                st[p0] = s0; st[p1] = s1;
            }
            __syncthreads();
        }

        // ===== P10: F11 = CRX(11,0): ctrl bit0, tgt bit11 =====
        crx_pass(st, t, 11, 0, cs[base + 47], sn[base + 47]);

        // ===== P11..P17: B_i = CRX(i,i-1), i=11..5: axis=12-i, cond=11-i =====
        #pragma unroll
        for (int i = 11; i >= 5; i--) {
            int pi = base + 48 + (11 - i);
            crx_pass(st, t, 12 - i, 11 - i, cs[pi], sn[pi]);
        }

        // ===== P18: local mega-pass: B4, B3, B2, B1 =====
        #pragma unroll
        for (int k = 0; k < 16; k++) v[k] = st[PHYS(t + (k << 8))];
        {   // B4 = CRX(4,3): ctrl t bit7, tgt k bit0
            int pi = base + 55;
            float c = cs[pi], s = sn[pi];
            if (t & 128) {
                #pragma unroll
                for (int k = 0; k < 16; k += 2) appRX(v[k], v[k | 1], c, s);
            }
        }
        {   // B3 = CRX(3,2): ctrl k0, tgt k1
            int pi = base + 56;
            float c = cs[pi], s = sn[pi];
            #pragma unroll
            for (int k = 0; k < 16; k++)
                if ((k & 1) && !(k & 2)) appRX(v[k], v[k | 2], c, s);
        }
        {   // B2 = CRX(2,1): ctrl k1, tgt k2
            int pi = base + 57;
            float c = cs[pi], s = sn[pi];
            #pragma unroll
            for (int k = 0; k < 16; k++)
                if ((k & 2) && !(k & 4)) appRX(v[k], v[k | 4], c, s);
        }
        {   // B1 = CRX(1,0): ctrl k2, tgt k3
            int pi = base + 58;
            float c = cs[pi], s = sn[pi];
            #pragma unroll
            for (int k = 0; k < 16; k++)
                if ((k & 4) && !(k & 8)) appRX(v[k], v[k | 8], c, s);
        }
        #pragma unroll
        for (int k = 0; k < 16; k++) st[PHYS(t + (k << 8))] = v[k];
        __syncthreads();

        // ===== P19: B0 = CRX(0,11): ctrl bit11, tgt bit0 =====
        crx_pass(st, t, 0, 11, cs[base + 59], sn[base + 59]);
    }

    // ================= expectations =================
    #pragma unroll
    for (int k = 0; k < 16; k++) v[k] = st[PHYS(t + (k << 8))];
    float nv[16], S = 0.0f;
    #pragma unroll
    for (int k = 0; k < 16; k++) {
        nv[k] = fmaf(v[k].x, v[k].x, v[k].y * v[k].y);
        S += nv[k];
    }

    // wires 0-3: k-bit pairs (register-local)
    #pragma unroll
    for (int w = 0; w < 4; w++) {
        int kbit = 1 << (3 - w);
        float rr = 0.f, ri = 0.f, rz = 0.f;
        #pragma unroll
        for (int k = 0; k < 16; k++) {
            if (!(k & kbit)) {
                float2 a = v[k], c = v[k | kbit];
                rr = fmaf(a.x, c.x, fmaf( a.y, c.y, rr));
                ri = fmaf(a.x, c.y, fmaf(-a.y, c.x, ri));
            }
            rz += (k & kbit) ? -nv[k] : nv[k];
        }
        wred(rbuf, w, warp, lane, rr, ri, rz);
    }

    // wires 4-6: warp-bit pairs (smem partner reads, bit=0 threads only)
    #pragma unroll
    for (int w = 4; w < 7; w++) {
        int pb = 11 - w;
        int own = (t >> pb) & 1;
        float rr = 0.f, ri = 0.f;
        if (!own) {
            int pt = t | (1 << pb);
            #pragma unroll
            for (int k = 0; k < 16; k++) {
                float2 c = st[PHYS(pt + (k << 8))];
                float2 a = v[k];
                rr = fmaf(a.x, c.x, fmaf( a.y, c.y, rr));
                ri = fmaf(a.x, c.y, fmaf(-a.y, c.x, ri));
            }
        }
        float rz = own ? -S : S;
        wred(rbuf, w, warp, lane, rr, ri, rz);
    }

    // wires 7-11: lane-bit pairs (shfl partner)
    #pragma unroll
    for (int w = 7; w < 12; w++) {
        int pb = 11 - w;
        int m = 1 << pb;
        int own = (t >> pb) & 1;
        float rr = 0.f, ri = 0.f;
        #pragma unroll
        for (int k = 0; k < 16; k++) {
            float px = __shfl_xor_sync(0xffffffffu, v[k].x, m);
            float py = __shfl_xor_sync(0xffffffffu, v[k].y, m);
            if (!own) {
                rr = fmaf(v[k].x, px, fmaf( v[k].y, py, rr));
                ri = fmaf(v[k].x, py, fmaf(-v[k].y, px, ri));
            }
        }
        float rz = own ? -S : S;
        wred(rbuf, w, warp, lane, rr, ri, rz);
    }

    __syncthreads();
    if (t < 36) {
        float a = 0.f;
        #pragma unroll
        for (int q = 0; q < 8; q++) a += rbuf[t * 8 + q];
        out[b * 36 + t] = (t < 24) ? 2.0f * a : a;
    }
}

extern "C" void kernel_launch(void* const* d_in, const int* in_sizes, int n_in,
                              void* d_out, int out_size) {
    const float* params = (const float*)d_in[0];   // (B, 240) float32
    const float* inputs = (const float*)d_in[1];   // (B, 12)  float32
    float* out = (float*)d_out;                    // (B, 36)  float32
    int B = in_sizes[0] / NPARAM;
    qfe_kernel<<<B, TPB>>>(params, inputs, out);
}

// round 6
// speedup vs baseline: 1.8454x; 1.8454x over previous
#include <cuda_runtime.h>

#define NQ     12
#define TPB    256
#define NPARAM 240          // 12 * 4 * 5
#define NLAYER 4
#define FM     0xffffffffu

#define SMEM_BYTES 68704

// new = A*v + B*p  (complex)
__device__ __forceinline__ float2 axpb(float2 A, float2 v, float2 B, float2 p) {
    return make_float2(
        fmaf(A.x, v.x, fmaf(-A.y, v.y, fmaf(B.x, p.x, -B.y * p.y))),
        fmaf(A.x, v.y, fmaf( A.y, v.x, fmaf(B.x, p.y,  B.y * p.x))));
}

__device__ __forceinline__ float2 cmulf(float2 a, float2 b) {
    return make_float2(fmaf(a.x, b.x, -a.y * b.y), fmaf(a.x, b.y, a.y * b.x));
}

// RX(theta) on a register pair: n0 = c*s0 - i s*s1 ; n1 = c*s1 - i s*s0
__device__ __forceinline__ void appRX(float2 &s0, float2 &s1, float c, float s) {
    float2 n0 = make_float2(fmaf(c, s0.x,  s * s1.y), fmaf(c, s0.y, -s * s1.x));
    float2 n1 = make_float2(fmaf(c, s1.x,  s * s0.y), fmaf(c, s1.y, -s * s0.x));
    s0 = n0; s1 = n1;
}

// M = Rz * Ry * Rx (gates applied in order Rx, Ry, Rz)
__device__ __forceinline__ void build_u(const float* cs, const float* sn, int pi,
        float2 &M00, float2 &M01, float2 &M10, float2 &M11) {
    float cx = cs[pi],     sx = sn[pi];
    float cy = cs[pi + 1], sy = sn[pi + 1];
    float cz = cs[pi + 2], sz = sn[pi + 2];
    float2 A00 = make_float2( cy * cx,  sy * sx);
    float2 A01 = make_float2(-sy * cx, -cy * sx);
    float2 A10 = make_float2( sy * cx, -cy * sx);
    float2 A11 = make_float2( cy * cx, -sy * sx);
    float2 ez  = make_float2(cz, -sz), ezc = make_float2(cz, sz);
    M00 = cmulf(ez,  A00); M01 = cmulf(ez,  A01);
    M10 = cmulf(ezc, A10); M11 = cmulf(ezc, A11);
}

// M <- RX(c,s) * M   (RX applied after M)
__device__ __forceinline__ void fuse_rx(float c, float s,
        float2 &M00, float2 &M01, float2 &M10, float2 &M11) {
    float2 W00 = make_float2(fmaf(c, M00.x,  s * M10.y), fmaf(c, M00.y, -s * M10.x));
    float2 W01 = make_float2(fmaf(c, M01.x,  s * M11.y), fmaf(c, M01.y, -s * M11.x));
    float2 W10 = make_float2(fmaf(c, M10.x,  s * M00.y), fmaf(c, M10.y, -s * M00.x));
    float2 W11 = make_float2(fmaf(c, M11.x,  s * M01.y), fmaf(c, M11.y, -s * M01.x));
    M00 = W00; M01 = W01; M10 = W10; M11 = W11;
}

__global__ void __launch_bounds__(TPB, 2) qfe_kernel(
    const float* __restrict__ params,   // (B, 240)
    const float* __restrict__ inputs,   // (B, 12)
    float* __restrict__ out)            // (B, 36)
{
    extern __shared__ float smem_raw[];
    float2* bufA = (float2*)smem_raw;           // 4096 float2 = 32 KB
    float2* bufB = bufA + 4096;                 // 32 KB
    float*  cs   = (float*)(bufB + 4096);       // 240
    float*  sn   = cs + NPARAM;                 // 240
    float*  eic  = sn + NPARAM;                 // 12
    float*  eis  = eic + NQ;                    // 12
    float*  rbuf = eis + NQ;                    // 288

    const int b = blockIdx.x;
    const int t = threadIdx.x;
    const int lane = t & 31, warp = t >> 5;

    // ---- stage all trig once per block
    if (t < NPARAM) {
        float h = 0.5f * params[b * NPARAM + t];
        sincosf(h, &sn[t], &cs[t]);
    } else if (t < NPARAM + NQ) {
        int i = t - NPARAM;
        float h = 0.5f * inputs[b * NQ + i];
        sincosf(h, &eis[i], &eic[i]);
    }
    __syncthreads();

    // ---- state resident in registers: idx = t | (k<<8); wire w <-> bit (11-w)
    float2 v[16];
    {
        // product state: RY(input_w) embedding applied to |0...0>
        float tp = 1.0f;
        #pragma unroll
        for (int w = 4; w < 12; w++)
            tp *= ((t >> (11 - w)) & 1) ? eis[w] : eic[w];
        #pragma unroll
        for (int k = 0; k < 16; k++) {
            float a = tp;
            #pragma unroll
            for (int w = 0; w < 4; w++)
                a *= ((k >> (3 - w)) & 1) ? eis[w] : eic[w];
            v[k] = make_float2(a, 0.0f);
        }
    }

    #pragma unroll 1
    for (int L = 0; L < NLAYER; L++) {
        const int base = 60 * L;

        // ===== U0..U3 on k bits (register-local) =====
        #pragma unroll
        for (int w = 0; w < 4; w++) {
            float2 M00, M01, M10, M11;
            build_u(cs, sn, base + 3 * w, M00, M01, M10, M11);
            int kb = 1 << (3 - w);
            #pragma unroll
            for (int k = 0; k < 16; k++) if (!(k & kb)) {
                float2 s0 = v[k], s1 = v[k | kb];
                v[k]      = axpb(M00, s0, M01, s1);
                v[k | kb] = axpb(M11, s1, M10, s0);
            }
        }
        // ===== F0,F1,F2 (ctrl k(3-i) -> tgt k(2-i), register-local) =====
        #pragma unroll
        for (int i = 0; i < 3; i++) {
            float c = cs[base + 36 + i], s = sn[base + 36 + i];
            int cb = 8 >> i, tb = 4 >> i;
            #pragma unroll
            for (int k = 0; k < 16; k++)
                if ((k & cb) && !(k & tb)) appRX(v[k], v[k | tb], c, s);
        }

        // ===== U4 + F3 : smem exchange axis bit7; F3 cond = k bit0 (per-k) =====
        {
            float2 M00, M01, M10, M11;
            build_u(cs, sn, base + 12, M00, M01, M10, M11);
            float2 W00 = M00, W01 = M01, W10 = M10, W11 = M11;
            fuse_rx(cs[base + 39], sn[base + 39], W00, W01, W10, W11);
            int own = (t >> 7) & 1;
            float2 Am = own ? M11 : M00, Bm = own ? M10 : M01;
            float2 Aw = own ? W11 : W00, Bw = own ? W10 : W01;
            #pragma unroll
            for (int k = 0; k < 16; k++) bufA[(k << 8) | t] = v[k];
            __syncthreads();
            int pt = t ^ 128;
            #pragma unroll
            for (int k = 0; k < 16; k++) {
                float2 p = bufA[(k << 8) | pt];
                v[k] = (k & 1) ? axpb(Aw, v[k], Bw, p) : axpb(Am, v[k], Bm, p);
            }
        }
        // ===== U5 + F4 (cond t bit7): smem axis bit6 =====
        {
            float2 M00, M01, M10, M11;
            build_u(cs, sn, base + 15, M00, M01, M10, M11);
            if (t & 128) fuse_rx(cs[base + 40], sn[base + 40], M00, M01, M10, M11);
            int own = (t >> 6) & 1;
            float2 A = own ? M11 : M00, B = own ? M10 : M01;
            #pragma unroll
            for (int k = 0; k < 16; k++) bufB[(k << 8) | t] = v[k];
            __syncthreads();
            int pt = t ^ 64;
            #pragma unroll
            for (int k = 0; k < 16; k++)
                v[k] = axpb(A, v[k], B, bufB[(k << 8) | pt]);
        }
        // ===== U6 + F5 (cond t bit6): smem axis bit5 =====
        {
            float2 M00, M01, M10, M11;
            build_u(cs, sn, base + 18, M00, M01, M10, M11);
            if (t & 64) fuse_rx(cs[base + 41], sn[base + 41], M00, M01, M10, M11);
            int own = (t >> 5) & 1;
            float2 A = own ? M11 : M00, B = own ? M10 : M01;
            #pragma unroll
            for (int k = 0; k < 16; k++) bufA[(k << 8) | t] = v[k];
            __syncthreads();
            int pt = t ^ 32;
            #pragma unroll
            for (int k = 0; k < 16; k++)
                v[k] = axpb(A, v[k], B, bufA[(k << 8) | pt]);
        }
        // ===== U7..U11 + F6..F10 : shfl, axis m=1<<(11-w), cond bit = m<<1 =====
        #pragma unroll
        for (int w = 7; w < 12; w++) {
            const int m = 1 << (11 - w);
            float2 M00, M01, M10, M11;
            build_u(cs, sn, base + 3 * w, M00, M01, M10, M11);
            if (t & (m << 1))
                fuse_rx(cs[base + 36 + w - 1], sn[base + 36 + w - 1], M00, M01, M10, M11);
            int own = (t & m) ? 1 : 0;
            float2 A = own ? M11 : M00, B = own ? M10 : M01;
            #pragma unroll
            for (int k = 0; k < 16; k++) {
                float px = __shfl_xor_sync(FM, v[k].x, m);
                float py = __shfl_xor_sync(FM, v[k].y, m);
                v[k] = axpb(A, v[k], B, make_float2(px, py));
            }
        }
        // ===== F11: ctrl t bit0, tgt k bit3 (register-local) =====
        {
            float c = cs[base + 47], s = sn[base + 47];
            if (t & 1) {
                #pragma unroll
                for (int k = 0; k < 8; k++) appRX(v[k], v[k | 8], c, s);
            }
        }
        // ===== B11..B8: shfl CRX, axis m=1<<(12-i), cond bit = m>>1 =====
        #pragma unroll
        for (int i = 11; i >= 8; i--) {
            const int m = 1 << (12 - i);
            float c = cs[base + 48 + (11 - i)], s = sn[base + 48 + (11 - i)];
            int cond = t & (m >> 1);
            #pragma unroll
            for (int k = 0; k < 16; k++) {
                float px = __shfl_xor_sync(FM, v[k].x, m);
                float py = __shfl_xor_sync(FM, v[k].y, m);
                if (cond)
                    v[k] = make_float2(fmaf(c, v[k].x,  s * py),
                                       fmaf(c, v[k].y, -s * px));
            }
        }
        // ===== B7: smem axis bit5, cond t bit4 =====
        {
            float c = cs[base + 52], s = sn[base + 52];
            #pragma unroll
            for (int k = 0; k < 16; k++) bufB[(k << 8) | t] = v[k];
            __syncthreads();
            if (t & 16) {
                int pt = t ^ 32;
                #pragma unroll
                for (int k = 0; k < 16; k++) {
                    float2 p = bufB[(k << 8) | pt];
                    v[k] = make_float2(fmaf(c, v[k].x,  s * p.y),
                                       fmaf(c, v[k].y, -s * p.x));
                }
            }
        }
        // ===== B6: smem axis bit6, cond t bit5 =====
        {
            float c = cs[base + 53], s = sn[base + 53];
            #pragma unroll
            for (int k = 0; k < 16; k++) bufA[(k << 8) | t] = v[k];
            __syncthreads();
            if (t & 32) {
                int pt = t ^ 64;
                #pragma unroll
                for (int k = 0; k < 16; k++) {
                    float2 p = bufA[(k << 8) | pt];
                    v[k] = make_float2(fmaf(c, v[k].x,  s * p.y),
                                       fmaf(c, v[k].y, -s * p.x));
                }
            }
        }
        // ===== B5: smem axis bit7, cond t bit6 =====
        {
            float c = cs[base + 54], s = sn[base + 54];
            #pragma unroll
            for (int k = 0; k < 16; k++) bufB[(k << 8) | t] = v[k];
            __syncthreads();
            if (t & 64) {
                int pt = t ^ 128;
                #pragma unroll
                for (int k = 0; k < 16; k++) {
                    float2 p = bufB[(k << 8) | pt];
                    v[k] = make_float2(fmaf(c, v[k].x,  s * p.y),
                                       fmaf(c, v[k].y, -s * p.x));
                }
            }
        }
        // ===== B4: ctrl t bit7, tgt k bit0 (register-local) =====
        {
            float c = cs[base + 55], s = sn[base + 55];
            if (t & 128) {
                #pragma unroll
                for (int k = 0; k < 16; k += 2) appRX(v[k], v[k | 1], c, s);
            }
        }
        // ===== B3,B2,B1: ctrl k(j) -> tgt k(j+1) (register-local) =====
        #pragma unroll
        for (int j = 0; j < 3; j++) {
            float c = cs[base + 56 + j], s = sn[base + 56 + j];
            int cb = 1 << j, tb = 2 << j;
            #pragma unroll
            for (int k = 0; k < 16; k++)
                if ((k & cb) && !(k & tb)) appRX(v[k], v[k | tb], c, s);
        }
        // ===== B0: ctrl k bit3, tgt lane bit0 (shfl, per-k predicate) =====
        {
            float c = cs[base + 59], s = sn[base + 59];
            #pragma unroll
            for (int k = 8; k < 16; k++) {
                float px = __shfl_xor_sync(FM, v[k].x, 1);
                float py = __shfl_xor_sync(FM, v[k].y, 1);
                v[k] = make_float2(fmaf(c, v[k].x,  s * py),
                                   fmaf(c, v[k].y, -s * px));
            }
        }
    }

    // ================= expectations =================
    // dump state once for warp-axis wires 4-6
    #pragma unroll
    for (int k = 0; k < 16; k++) bufA[(k << 8) | t] = v[k];
    __syncthreads();

    float nv[16], S = 0.0f;
    #pragma unroll
    for (int k = 0; k < 16; k++) {
        nv[k] = fmaf(v[k].x, v[k].x, v[k].y * v[k].y);
        S += nv[k];
    }

    // wires 0-3: k-bit pairs (register-local)
    #pragma unroll
    for (int w = 0; w < 4; w++) {
        int kb = 1 << (3 - w);
        float rr = 0.f, ri = 0.f, rz = 0.f;
        #pragma unroll
        for (int k = 0; k < 16; k++) {
            if (!(k & kb)) {
                float2 a = v[k], c = v[k | kb];
                rr = fmaf(a.x, c.x, fmaf( a.y, c.y, rr));
                ri = fmaf(a.x, c.y, fmaf(-a.y, c.x, ri));
            }
            rz += (k & kb) ? -nv[k] : nv[k];
        }
        #pragma unroll
        for (int off = 16; off; off >>= 1) {
            rr += __shfl_down_sync(FM, rr, off);
            ri += __shfl_down_sync(FM, ri, off);
            rz += __shfl_down_sync(FM, rz, off);
        }
        if (lane == 0) {
            rbuf[w * 8 + warp]       = rr;
            rbuf[96 + w * 8 + warp]  = ri;
            rbuf[192 + w * 8 + warp] = rz;
        }
    }

    // wires 4-6: warp-bit pairs (partner from bufA; own-bit==0 threads only)
    #pragma unroll
    for (int w = 4; w < 7; w++) {
        int pb = 11 - w;
        int own = (t >> pb) & 1;
        float rr = 0.f, ri = 0.f;
        if (!own) {
            int pt = t | (1 << pb);
            #pragma unroll
            for (int k = 0; k < 16; k++) {
                float2 c = bufA[(k << 8) | pt];
                float2 a = v[k];
                rr = fmaf(a.x, c.x, fmaf( a.y, c.y, rr));
                ri = fmaf(a.x, c.y, fmaf(-a.y, c.x, ri));
            }
        }
        float rz = own ? -S : S;
        #pragma unroll
        for (int off = 16; off; off >>= 1) {
            rr += __shfl_down_sync(FM, rr, off);
            ri += __shfl_down_sync(FM, ri, off);
            rz += __shfl_down_sync(FM, rz, off);
        }
        if (lane == 0) {
            rbuf[w * 8 + warp]       = rr;
            rbuf[96 + w * 8 + warp]  = ri;
            rbuf[192 + w * 8 + warp] = rz;
        }
    }

    // wires 7-11: lane-bit pairs (shfl partner)
    #pragma unroll
    for (int w = 7; w < 12; w++) {
        int pb = 11 - w;
        int m = 1 << pb;
        int own = (t >> pb) & 1;
        float rr = 0.f, ri = 0.f;
        #pragma unroll
        for (int k = 0; k < 16; k++) {
            float px = __shfl_xor_sync(FM, v[k].x, m);
            float py = __shfl_xor_sync(FM, v[k].y, m);
            if (!own) {
                rr = fmaf(v[k].x, px, fmaf( v[k].y, py, rr));
                ri = fmaf(v[k].x, py, fmaf(-v[k].y, px, ri));
            }
        }
        float rz = own ? -S : S;
        #pragma unroll
        for (int off = 16; off; off >>= 1) {
            rr += __shfl_down_sync(FM, rr, off);
            ri += __shfl_down_sync(FM, ri, off);
            rz += __shfl_down_sync(FM, rz, off);
        }
        if (lane == 0) {
            rbuf[w * 8 + warp]       = rr;
            rbuf[96 + w * 8 + warp]  = ri;
            rbuf[192 + w * 8 + warp] = rz;
        }
    }

    __syncthreads();
    if (t < 36) {
        float a = 0.f;
        #pragma unroll
        for (int q = 0; q < 8; q++) a += rbuf[t * 8 + q];
        out[b * 36 + t] = (t < 24) ? 2.0f * a : a;
    }
}

extern "C" void kernel_launch(void* const* d_in, const int* in_sizes, int n_in,
                              void* d_out, int out_size) {
    const float* params = (const float*)d_in[0];   // (B, 240) float32
    const float* inputs = (const float*)d_in[1];   // (B, 12)  float32
    float* out = (float*)d_out;                    // (B, 36)  float32
    int B = in_sizes[0] / NPARAM;
    static bool attr_set = false;
    if (!attr_set) {
        cudaFuncSetAttribute(qfe_kernel,
                             cudaFuncAttributeMaxDynamicSharedMemorySize,
                             SMEM_BYTES);
        attr_set = true;
    }
    qfe_kernel<<<B, TPB, SMEM_BYTES>>>(params, inputs, out);
}